// round 12
// baseline (speedup 1.0000x reference)
#include <cuda_runtime.h>

// Problem constants
#define IN_SZ   8192
#define OUT_SZ  8192
#define OUT4    (OUT_SZ / 4)            // 2048 float4 columns
// sigmoid(2.0)
#define SIG_TAU 0.8807970779778823f

// Tile shape — FROZEN R8 config: 32 float4 cols x 512 rows per tile,
// 8 warps split the rows (64 rows each). 64 x 16 = 1024 tiles.
#define THREADS        256
#define WARPS          8
#define SLAB_COLS4     32
#define NSLAB          (OUT4 / SLAB_COLS4)        // 64 column slabs
#define RGROUPS        16                         // split-K depth
#define ROWS_PER_BLOCK (IN_SZ / RGROUPS)          // 512
#define ROWS_PER_WARP  (ROWS_PER_BLOCK / WARPS)   // 64
#define NTILES         (NSLAB * RGROUPS)          // 1024
#define MAIN_GRID      (NTILES / 2)               // 512 blocks, 2 tiles each

// Deterministic split-K scratch: 16 x 2048 float4 = 512 KB.
__device__ float4 g_partial4[RGROUPS * OUT4];

// Persistent-style main: 512 co-resident blocks (single wave), each runs two
// tiles (bid, bid+512) with the exact R8 inner loop -> bitwise-identical sums.
__global__ __launch_bounds__(THREADS, 1)
void ostl_main_kernel(const float* __restrict__ x,
                      const float* __restrict__ J,
                      const float* __restrict__ W,
                      float* __restrict__ Jout)
{
    __shared__ float  sx[ROWS_PER_BLOCK];              // 2 KB
    __shared__ float4 sacc[WARPS][SLAB_COLS4];         // 4 KB

    const int lane = threadIdx.x & 31;
    const int w    = threadIdx.x >> 5;                 // warp 0..7

    const float4* __restrict__ W4 = (const float4*)W;
    const float4* __restrict__ J4 = (const float4*)J;
    float4*       __restrict__ O4 = (float4*)Jout;

    #pragma unroll
    for (int t = 0; t < 2; ++t) {
        const int tile = blockIdx.x + t * MAIN_GRID;   // 0..1023
        const int slab = tile & (NSLAB - 1);           // column slab 0..63
        const int rg   = tile >> 6;                    // row group 0..15

        const int c    = slab * SLAB_COLS4 + lane;     // float4 column
        const int rg0  = rg * ROWS_PER_BLOCK;          // row base

        if (t > 0) __syncthreads();                    // sx reuse guard
        for (int i = threadIdx.x; i < ROWS_PER_BLOCK; i += THREADS)
            sx[i] = x[rg0 + i];
        __syncthreads();

        float4 acc = make_float4(0.f, 0.f, 0.f, 0.f);
        const int rbase = w * ROWS_PER_WARP;
        int idx = (rg0 + rbase) * OUT4 + c;            // max ~16.7M -> fits int

        #pragma unroll 4
        for (int r = 0; r < ROWS_PER_WARP; ++r, idx += OUT4) {
            const float xi = sx[rbase + r];
            const float4 wv = W4[idx];
            const float4 jv = J4[idx];

            acc.x = fmaf(xi, wv.x, acc.x);
            acc.y = fmaf(xi, wv.y, acc.y);
            acc.z = fmaf(xi, wv.z, acc.z);
            acc.w = fmaf(xi, wv.w, acc.w);

            float4 o;
            o.x = fmaf(SIG_TAU, jv.x, xi);
            o.y = fmaf(SIG_TAU, jv.y, xi);
            o.z = fmaf(SIG_TAU, jv.z, xi);
            o.w = fmaf(SIG_TAU, jv.w, xi);
            O4[idx] = o;
        }

        // In-block cross-warp reduction in FIXED warp order -> deterministic.
        sacc[w][lane] = acc;
        __syncthreads();

        if (w == 0) {
            float4 a = sacc[0][lane];
            #pragma unroll
            for (int tt = 1; tt < WARPS; ++tt) {
                const float4 b = sacc[tt][lane];
                a.x += b.x; a.y += b.y; a.z += b.z; a.w += b.w;
            }
            g_partial4[rg * OUT4 + c] = a;
        }
    }
}

// Epilogue (PDL secondary): one partial-load per thread; fixed slice-order
// combine through shared memory -> arithmetic identical to prior rounds.
#define EPI_THREADS 256
#define EPI_COLS4   16                       // float4 columns per block
#define EPI_GRID    (OUT4 / EPI_COLS4)       // 128 blocks
__global__ __launch_bounds__(EPI_THREADS, 1)
void ostl_epilogue_kernel(const float* __restrict__ u,
                          float* __restrict__ out_u,
                          float* __restrict__ out_s)
{
    __shared__ float4 sacc[RGROUPS][EPI_COLS4];

    const int lc = threadIdx.x & (EPI_COLS4 - 1);    // local column 0..15
    const int q  = threadIdx.x >> 4;                 // slice 0..15
    const int c  = blockIdx.x * EPI_COLS4 + lc;      // float4 column

    // Pre-load u before the dependency sync (input, untouched by main).
    float4 uu = make_float4(0.f, 0.f, 0.f, 0.f);
    if (q == 0) uu = ((const float4*)u)[c];

    cudaGridDependencySynchronize();

    sacc[q][lc] = g_partial4[q * OUT4 + c];          // one load per thread
    __syncthreads();

    if (q == 0) {
        float4 a = sacc[0][lc];
        #pragma unroll
        for (int t = 1; t < RGROUPS; ++t) {          // fixed slice order
            const float4 b = sacc[t][lc];
            a.x += b.x; a.y += b.y; a.z += b.z; a.w += b.w;
        }
        float4 uo, so;
        {
            float un;
            un = fmaf(SIG_TAU, uu.x, a.x); so.x = (un - 1.0f) > 0.f ? 1.f : 0.f; uo.x = un - so.x;
            un = fmaf(SIG_TAU, uu.y, a.y); so.y = (un - 1.0f) > 0.f ? 1.f : 0.f; uo.y = un - so.y;
            un = fmaf(SIG_TAU, uu.z, a.z); so.z = (un - 1.0f) > 0.f ? 1.f : 0.f; uo.z = un - so.z;
            un = fmaf(SIG_TAU, uu.w, a.w); so.w = (un - 1.0f) > 0.f ? 1.f : 0.f; uo.w = un - so.w;
        }
        ((float4*)out_u)[c] = uo;
        ((float4*)out_s)[c] = so;
    }
}

extern "C" void kernel_launch(void* const* d_in, const int* in_sizes, int n_in,
                              void* d_out, int out_size)
{
    const float* x = (const float*)d_in[0];
    const float* u = (const float*)d_in[1];
    const float* J = (const float*)d_in[2];
    const float* W = (const float*)d_in[3];

    float* out   = (float*)d_out;
    float* out_u = out;                                   // [0, 8192)
    float* out_J = out + OUT_SZ;                          // [8192, 8192+64M)
    float* out_s = out + OUT_SZ + (size_t)IN_SZ * OUT_SZ; // last 8192

    ostl_main_kernel<<<MAIN_GRID, THREADS>>>(x, J, W, out_J);

    // PDL launch: epilogue dispatches while main drains.
    cudaLaunchAttribute attrs[1];
    attrs[0].id = cudaLaunchAttributeProgrammaticStreamSerialization;
    attrs[0].val.programmaticStreamSerializationAllowed = 1;

    cudaLaunchConfig_t cfg = {};
    cfg.gridDim  = dim3(EPI_GRID, 1, 1);
    cfg.blockDim = dim3(EPI_THREADS, 1, 1);
    cfg.dynamicSmemBytes = 0;
    cfg.stream   = 0;
    cfg.attrs    = attrs;
    cfg.numAttrs = 1;
    cudaLaunchKernelEx(&cfg, ostl_epilogue_kernel, u, out_u, out_s);
}

// round 13
// speedup vs baseline: 1.0774x; 1.0774x over previous
#include <cuda_runtime.h>

// Problem constants
#define IN_SZ   8192
#define OUT_SZ  8192
#define OUT4    (OUT_SZ / 4)            // 2048 float4 columns
// sigmoid(2.0)
#define SIG_TAU 0.8807970779778823f

// Main-kernel tiling — R8/R11 config (grid 64x16, 256 thr). Only change vs
// R11: unroll depth 4 -> 8 (same accumulation order -> bitwise identical).
#define THREADS        256
#define WARPS          8
#define SLAB_COLS4     32               // float4 columns per block (one per lane)
#define NSLAB          (OUT4 / SLAB_COLS4)        // 64 column slabs
#define RGROUPS        16               // row groups (split-K depth)
#define ROWS_PER_BLOCK (IN_SZ / RGROUPS)          // 512
#define ROWS_PER_WARP  (ROWS_PER_BLOCK / WARPS)   // 64

// Deterministic split-K scratch: 16 x 2048 float4 = 512 KB.
__device__ float4 g_partial4[RGROUPS * OUT4];

__global__ __launch_bounds__(THREADS, 1)
void ostl_main_kernel(const float* __restrict__ x,
                      const float* __restrict__ J,
                      const float* __restrict__ W,
                      float* __restrict__ Jout)
{
    __shared__ float  sx[ROWS_PER_BLOCK];              // 2 KB
    __shared__ float4 sacc[WARPS][SLAB_COLS4];         // 4 KB

    const int lane = threadIdx.x & 31;
    const int w    = threadIdx.x >> 5;                 // warp 0..7
    const int c    = blockIdx.x * SLAB_COLS4 + lane;   // float4 column
    const int rg0  = blockIdx.y * ROWS_PER_BLOCK;      // block row base

    for (int i = threadIdx.x; i < ROWS_PER_BLOCK; i += THREADS)
        sx[i] = x[rg0 + i];
    __syncthreads();

    const float4* __restrict__ W4 = (const float4*)W;
    const float4* __restrict__ J4 = (const float4*)J;
    float4*       __restrict__ O4 = (float4*)Jout;

    float4 acc = make_float4(0.f, 0.f, 0.f, 0.f);
    const int rbase = w * ROWS_PER_WARP;               // warp's rows within block
    int idx = (rg0 + rbase) * OUT4 + c;                // max ~16.7M -> fits int

    #pragma unroll 8
    for (int r = 0; r < ROWS_PER_WARP; ++r, idx += OUT4) {
        const float xi = sx[rbase + r];
        const float4 wv = W4[idx];
        const float4 jv = J4[idx];

        acc.x = fmaf(xi, wv.x, acc.x);
        acc.y = fmaf(xi, wv.y, acc.y);
        acc.z = fmaf(xi, wv.z, acc.z);
        acc.w = fmaf(xi, wv.w, acc.w);

        float4 o;
        o.x = fmaf(SIG_TAU, jv.x, xi);
        o.y = fmaf(SIG_TAU, jv.y, xi);
        o.z = fmaf(SIG_TAU, jv.z, xi);
        o.w = fmaf(SIG_TAU, jv.w, xi);
        O4[idx] = o;
    }

    // In-block cross-warp reduction in FIXED warp order -> deterministic.
    sacc[w][lane] = acc;
    __syncthreads();

    if (w == 0) {
        float4 a = sacc[0][lane];
        #pragma unroll
        for (int t = 1; t < WARPS; ++t) {
            const float4 b = sacc[t][lane];
            a.x += b.x; a.y += b.y; a.z += b.z; a.w += b.w;
        }
        g_partial4[blockIdx.y * OUT4 + c] = a;
    }
}

// Epilogue (PDL secondary): one partial-load per thread; fixed slice-order
// combine through shared memory -> arithmetic identical to prior rounds.
#define EPI_THREADS 256
#define EPI_COLS4   16                       // float4 columns per block
#define EPI_GRID    (OUT4 / EPI_COLS4)       // 128 blocks
__global__ __launch_bounds__(EPI_THREADS, 1)
void ostl_epilogue_kernel(const float* __restrict__ u,
                          float* __restrict__ out_u,
                          float* __restrict__ out_s)
{
    __shared__ float4 sacc[RGROUPS][EPI_COLS4];

    const int lc = threadIdx.x & (EPI_COLS4 - 1);    // local column 0..15
    const int q  = threadIdx.x >> 4;                 // slice 0..15
    const int c  = blockIdx.x * EPI_COLS4 + lc;      // float4 column

    // Pre-load u before the dependency sync (input, untouched by main).
    float4 uu = make_float4(0.f, 0.f, 0.f, 0.f);
    if (q == 0) uu = ((const float4*)u)[c];

    cudaGridDependencySynchronize();

    sacc[q][lc] = g_partial4[q * OUT4 + c];          // one load per thread
    __syncthreads();

    if (q == 0) {
        float4 a = sacc[0][lc];
        #pragma unroll
        for (int t = 1; t < RGROUPS; ++t) {          // fixed slice order
            const float4 b = sacc[t][lc];
            a.x += b.x; a.y += b.y; a.z += b.z; a.w += b.w;
        }
        float4 uo, so;
        {
            float un;
            un = fmaf(SIG_TAU, uu.x, a.x); so.x = (un - 1.0f) > 0.f ? 1.f : 0.f; uo.x = un - so.x;
            un = fmaf(SIG_TAU, uu.y, a.y); so.y = (un - 1.0f) > 0.f ? 1.f : 0.f; uo.y = un - so.y;
            un = fmaf(SIG_TAU, uu.z, a.z); so.z = (un - 1.0f) > 0.f ? 1.f : 0.f; uo.z = un - so.z;
            un = fmaf(SIG_TAU, uu.w, a.w); so.w = (un - 1.0f) > 0.f ? 1.f : 0.f; uo.w = un - so.w;
        }
        ((float4*)out_u)[c] = uo;
        ((float4*)out_s)[c] = so;
    }
}

extern "C" void kernel_launch(void* const* d_in, const int* in_sizes, int n_in,
                              void* d_out, int out_size)
{
    const float* x = (const float*)d_in[0];
    const float* u = (const float*)d_in[1];
    const float* J = (const float*)d_in[2];
    const float* W = (const float*)d_in[3];

    float* out   = (float*)d_out;
    float* out_u = out;                                   // [0, 8192)
    float* out_J = out + OUT_SZ;                          // [8192, 8192+64M)
    float* out_s = out + OUT_SZ + (size_t)IN_SZ * OUT_SZ; // last 8192

    dim3 grid(NSLAB, RGROUPS);                            // 64 x 16 = 1024 blocks
    ostl_main_kernel<<<grid, THREADS>>>(x, J, W, out_J);

    // PDL launch: epilogue dispatches while main drains.
    cudaLaunchAttribute attrs[1];
    attrs[0].id = cudaLaunchAttributeProgrammaticStreamSerialization;
    attrs[0].val.programmaticStreamSerializationAllowed = 1;

    cudaLaunchConfig_t cfg = {};
    cfg.gridDim  = dim3(EPI_GRID, 1, 1);
    cfg.blockDim = dim3(EPI_THREADS, 1, 1);
    cfg.dynamicSmemBytes = 0;
    cfg.stream   = 0;
    cfg.attrs    = attrs;
    cfg.numAttrs = 1;
    cudaLaunchKernelEx(&cfg, ostl_epilogue_kernel, u, out_u, out_s);
}

// round 14
// speedup vs baseline: 1.0827x; 1.0049x over previous
#include <cuda_runtime.h>

// Problem constants
#define IN_SZ   8192
#define OUT_SZ  8192
#define OUT4    (OUT_SZ / 4)            // 2048 float4 columns
// sigmoid(2.0)
#define SIG_TAU 0.8807970779778823f

// Main-kernel tiling — R8/R11 config (grid 64x16, 256 thr). Only change vs
// R13: unroll depth 8 -> 16 (same accumulation order -> bitwise identical).
#define THREADS        256
#define WARPS          8
#define SLAB_COLS4     32               // float4 columns per block (one per lane)
#define NSLAB          (OUT4 / SLAB_COLS4)        // 64 column slabs
#define RGROUPS        16               // row groups (split-K depth)
#define ROWS_PER_BLOCK (IN_SZ / RGROUPS)          // 512
#define ROWS_PER_WARP  (ROWS_PER_BLOCK / WARPS)   // 64

// Deterministic split-K scratch: 16 x 2048 float4 = 512 KB.
__device__ float4 g_partial4[RGROUPS * OUT4];

__global__ __launch_bounds__(THREADS, 1)
void ostl_main_kernel(const float* __restrict__ x,
                      const float* __restrict__ J,
                      const float* __restrict__ W,
                      float* __restrict__ Jout)
{
    __shared__ float  sx[ROWS_PER_BLOCK];              // 2 KB
    __shared__ float4 sacc[WARPS][SLAB_COLS4];         // 4 KB

    const int lane = threadIdx.x & 31;
    const int w    = threadIdx.x >> 5;                 // warp 0..7
    const int c    = blockIdx.x * SLAB_COLS4 + lane;   // float4 column
    const int rg0  = blockIdx.y * ROWS_PER_BLOCK;      // block row base

    for (int i = threadIdx.x; i < ROWS_PER_BLOCK; i += THREADS)
        sx[i] = x[rg0 + i];
    __syncthreads();

    const float4* __restrict__ W4 = (const float4*)W;
    const float4* __restrict__ J4 = (const float4*)J;
    float4*       __restrict__ O4 = (float4*)Jout;

    float4 acc = make_float4(0.f, 0.f, 0.f, 0.f);
    const int rbase = w * ROWS_PER_WARP;               // warp's rows within block
    int idx = (rg0 + rbase) * OUT4 + c;                // max ~16.7M -> fits int

    #pragma unroll 16
    for (int r = 0; r < ROWS_PER_WARP; ++r, idx += OUT4) {
        const float xi = sx[rbase + r];
        const float4 wv = W4[idx];
        const float4 jv = J4[idx];

        acc.x = fmaf(xi, wv.x, acc.x);
        acc.y = fmaf(xi, wv.y, acc.y);
        acc.z = fmaf(xi, wv.z, acc.z);
        acc.w = fmaf(xi, wv.w, acc.w);

        float4 o;
        o.x = fmaf(SIG_TAU, jv.x, xi);
        o.y = fmaf(SIG_TAU, jv.y, xi);
        o.z = fmaf(SIG_TAU, jv.z, xi);
        o.w = fmaf(SIG_TAU, jv.w, xi);
        O4[idx] = o;
    }

    // In-block cross-warp reduction in FIXED warp order -> deterministic.
    sacc[w][lane] = acc;
    __syncthreads();

    if (w == 0) {
        float4 a = sacc[0][lane];
        #pragma unroll
        for (int t = 1; t < WARPS; ++t) {
            const float4 b = sacc[t][lane];
            a.x += b.x; a.y += b.y; a.z += b.z; a.w += b.w;
        }
        g_partial4[blockIdx.y * OUT4 + c] = a;
    }
}

// Epilogue (PDL secondary): one partial-load per thread; fixed slice-order
// combine through shared memory -> arithmetic identical to prior rounds.
#define EPI_THREADS 256
#define EPI_COLS4   16                       // float4 columns per block
#define EPI_GRID    (OUT4 / EPI_COLS4)       // 128 blocks
__global__ __launch_bounds__(EPI_THREADS, 1)
void ostl_epilogue_kernel(const float* __restrict__ u,
                          float* __restrict__ out_u,
                          float* __restrict__ out_s)
{
    __shared__ float4 sacc[RGROUPS][EPI_COLS4];

    const int lc = threadIdx.x & (EPI_COLS4 - 1);    // local column 0..15
    const int q  = threadIdx.x >> 4;                 // slice 0..15
    const int c  = blockIdx.x * EPI_COLS4 + lc;      // float4 column

    // Pre-load u before the dependency sync (input, untouched by main).
    float4 uu = make_float4(0.f, 0.f, 0.f, 0.f);
    if (q == 0) uu = ((const float4*)u)[c];

    cudaGridDependencySynchronize();

    sacc[q][lc] = g_partial4[q * OUT4 + c];          // one load per thread
    __syncthreads();

    if (q == 0) {
        float4 a = sacc[0][lc];
        #pragma unroll
        for (int t = 1; t < RGROUPS; ++t) {          // fixed slice order
            const float4 b = sacc[t][lc];
            a.x += b.x; a.y += b.y; a.z += b.z; a.w += b.w;
        }
        float4 uo, so;
        {
            float un;
            un = fmaf(SIG_TAU, uu.x, a.x); so.x = (un - 1.0f) > 0.f ? 1.f : 0.f; uo.x = un - so.x;
            un = fmaf(SIG_TAU, uu.y, a.y); so.y = (un - 1.0f) > 0.f ? 1.f : 0.f; uo.y = un - so.y;
            un = fmaf(SIG_TAU, uu.z, a.z); so.z = (un - 1.0f) > 0.f ? 1.f : 0.f; uo.z = un - so.z;
            un = fmaf(SIG_TAU, uu.w, a.w); so.w = (un - 1.0f) > 0.f ? 1.f : 0.f; uo.w = un - so.w;
        }
        ((float4*)out_u)[c] = uo;
        ((float4*)out_s)[c] = so;
    }
}

extern "C" void kernel_launch(void* const* d_in, const int* in_sizes, int n_in,
                              void* d_out, int out_size)
{
    const float* x = (const float*)d_in[0];
    const float* u = (const float*)d_in[1];
    const float* J = (const float*)d_in[2];
    const float* W = (const float*)d_in[3];

    float* out   = (float*)d_out;
    float* out_u = out;                                   // [0, 8192)
    float* out_J = out + OUT_SZ;                          // [8192, 8192+64M)
    float* out_s = out + OUT_SZ + (size_t)IN_SZ * OUT_SZ; // last 8192

    dim3 grid(NSLAB, RGROUPS);                            // 64 x 16 = 1024 blocks
    ostl_main_kernel<<<grid, THREADS>>>(x, J, W, out_J);

    // PDL launch: epilogue dispatches while main drains.
    cudaLaunchAttribute attrs[1];
    attrs[0].id = cudaLaunchAttributeProgrammaticStreamSerialization;
    attrs[0].val.programmaticStreamSerializationAllowed = 1;

    cudaLaunchConfig_t cfg = {};
    cfg.gridDim  = dim3(EPI_GRID, 1, 1);
    cfg.blockDim = dim3(EPI_THREADS, 1, 1);
    cfg.dynamicSmemBytes = 0;
    cfg.stream   = 0;
    cfg.attrs    = attrs;
    cfg.numAttrs = 1;
    cudaLaunchKernelEx(&cfg, ostl_epilogue_kernel, u, out_u, out_s);
}

// round 15
// speedup vs baseline: 1.0830x; 1.0003x over previous
#include <cuda_runtime.h>

// Problem constants
#define IN_SZ   8192
#define OUT_SZ  8192
#define OUT4    (OUT_SZ / 4)            // 2048 float4 columns
// sigmoid(2.0)
#define SIG_TAU 0.8807970779778823f

// Main-kernel tiling — R8/R11 config (grid 64x16, 256 thr). Only change vs
// R14: unroll depth 16 -> 32 (same accumulation order -> bitwise identical).
#define THREADS        256
#define WARPS          8
#define SLAB_COLS4     32               // float4 columns per block (one per lane)
#define NSLAB          (OUT4 / SLAB_COLS4)        // 64 column slabs
#define RGROUPS        16               // row groups (split-K depth)
#define ROWS_PER_BLOCK (IN_SZ / RGROUPS)          // 512
#define ROWS_PER_WARP  (ROWS_PER_BLOCK / WARPS)   // 64

// Deterministic split-K scratch: 16 x 2048 float4 = 512 KB.
__device__ float4 g_partial4[RGROUPS * OUT4];

__global__ __launch_bounds__(THREADS, 1)
void ostl_main_kernel(const float* __restrict__ x,
                      const float* __restrict__ J,
                      const float* __restrict__ W,
                      float* __restrict__ Jout)
{
    __shared__ float  sx[ROWS_PER_BLOCK];              // 2 KB
    __shared__ float4 sacc[WARPS][SLAB_COLS4];         // 4 KB

    const int lane = threadIdx.x & 31;
    const int w    = threadIdx.x >> 5;                 // warp 0..7
    const int c    = blockIdx.x * SLAB_COLS4 + lane;   // float4 column
    const int rg0  = blockIdx.y * ROWS_PER_BLOCK;      // block row base

    for (int i = threadIdx.x; i < ROWS_PER_BLOCK; i += THREADS)
        sx[i] = x[rg0 + i];
    __syncthreads();

    const float4* __restrict__ W4 = (const float4*)W;
    const float4* __restrict__ J4 = (const float4*)J;
    float4*       __restrict__ O4 = (float4*)Jout;

    float4 acc = make_float4(0.f, 0.f, 0.f, 0.f);
    const int rbase = w * ROWS_PER_WARP;               // warp's rows within block
    int idx = (rg0 + rbase) * OUT4 + c;                // max ~16.7M -> fits int

    #pragma unroll 32
    for (int r = 0; r < ROWS_PER_WARP; ++r, idx += OUT4) {
        const float xi = sx[rbase + r];
        const float4 wv = W4[idx];
        const float4 jv = J4[idx];

        acc.x = fmaf(xi, wv.x, acc.x);
        acc.y = fmaf(xi, wv.y, acc.y);
        acc.z = fmaf(xi, wv.z, acc.z);
        acc.w = fmaf(xi, wv.w, acc.w);

        float4 o;
        o.x = fmaf(SIG_TAU, jv.x, xi);
        o.y = fmaf(SIG_TAU, jv.y, xi);
        o.z = fmaf(SIG_TAU, jv.z, xi);
        o.w = fmaf(SIG_TAU, jv.w, xi);
        O4[idx] = o;
    }

    // In-block cross-warp reduction in FIXED warp order -> deterministic.
    sacc[w][lane] = acc;
    __syncthreads();

    if (w == 0) {
        float4 a = sacc[0][lane];
        #pragma unroll
        for (int t = 1; t < WARPS; ++t) {
            const float4 b = sacc[t][lane];
            a.x += b.x; a.y += b.y; a.z += b.z; a.w += b.w;
        }
        g_partial4[blockIdx.y * OUT4 + c] = a;
    }
}

// Epilogue (PDL secondary): one partial-load per thread; fixed slice-order
// combine through shared memory -> arithmetic identical to prior rounds.
#define EPI_THREADS 256
#define EPI_COLS4   16                       // float4 columns per block
#define EPI_GRID    (OUT4 / EPI_COLS4)       // 128 blocks
__global__ __launch_bounds__(EPI_THREADS, 1)
void ostl_epilogue_kernel(const float* __restrict__ u,
                          float* __restrict__ out_u,
                          float* __restrict__ out_s)
{
    __shared__ float4 sacc[RGROUPS][EPI_COLS4];

    const int lc = threadIdx.x & (EPI_COLS4 - 1);    // local column 0..15
    const int q  = threadIdx.x >> 4;                 // slice 0..15
    const int c  = blockIdx.x * EPI_COLS4 + lc;      // float4 column

    // Pre-load u before the dependency sync (input, untouched by main).
    float4 uu = make_float4(0.f, 0.f, 0.f, 0.f);
    if (q == 0) uu = ((const float4*)u)[c];

    cudaGridDependencySynchronize();

    sacc[q][lc] = g_partial4[q * OUT4 + c];          // one load per thread
    __syncthreads();

    if (q == 0) {
        float4 a = sacc[0][lc];
        #pragma unroll
        for (int t = 1; t < RGROUPS; ++t) {          // fixed slice order
            const float4 b = sacc[t][lc];
            a.x += b.x; a.y += b.y; a.z += b.z; a.w += b.w;
        }
        float4 uo, so;
        {
            float un;
            un = fmaf(SIG_TAU, uu.x, a.x); so.x = (un - 1.0f) > 0.f ? 1.f : 0.f; uo.x = un - so.x;
            un = fmaf(SIG_TAU, uu.y, a.y); so.y = (un - 1.0f) > 0.f ? 1.f : 0.f; uo.y = un - so.y;
            un = fmaf(SIG_TAU, uu.z, a.z); so.z = (un - 1.0f) > 0.f ? 1.f : 0.f; uo.z = un - so.z;
            un = fmaf(SIG_TAU, uu.w, a.w); so.w = (un - 1.0f) > 0.f ? 1.f : 0.f; uo.w = un - so.w;
        }
        ((float4*)out_u)[c] = uo;
        ((float4*)out_s)[c] = so;
    }
}

extern "C" void kernel_launch(void* const* d_in, const int* in_sizes, int n_in,
                              void* d_out, int out_size)
{
    const float* x = (const float*)d_in[0];
    const float* u = (const float*)d_in[1];
    const float* J = (const float*)d_in[2];
    const float* W = (const float*)d_in[3];

    float* out   = (float*)d_out;
    float* out_u = out;                                   // [0, 8192)
    float* out_J = out + OUT_SZ;                          // [8192, 8192+64M)
    float* out_s = out + OUT_SZ + (size_t)IN_SZ * OUT_SZ; // last 8192

    dim3 grid(NSLAB, RGROUPS);                            // 64 x 16 = 1024 blocks
    ostl_main_kernel<<<grid, THREADS>>>(x, J, W, out_J);

    // PDL launch: epilogue dispatches while main drains.
    cudaLaunchAttribute attrs[1];
    attrs[0].id = cudaLaunchAttributeProgrammaticStreamSerialization;
    attrs[0].val.programmaticStreamSerializationAllowed = 1;

    cudaLaunchConfig_t cfg = {};
    cfg.gridDim  = dim3(EPI_GRID, 1, 1);
    cfg.blockDim = dim3(EPI_THREADS, 1, 1);
    cfg.dynamicSmemBytes = 0;
    cfg.stream   = 0;
    cfg.attrs    = attrs;
    cfg.numAttrs = 1;
    cudaLaunchKernelEx(&cfg, ostl_epilogue_kernel, u, out_u, out_s);
}

// round 16
// speedup vs baseline: 1.1120x; 1.0267x over previous
#include <cuda_runtime.h>

// Problem constants
#define IN_SZ   8192
#define OUT_SZ  8192
#define OUT4    (OUT_SZ / 4)            // 2048 float4 columns
// sigmoid(2.0)
#define SIG_TAU 0.8807970779778823f

// Main-kernel tiling: SMALL blocks to shrink the end-of-kernel drain ramp.
// Tile = 32 float4 cols x 128 rows (196 KB traffic/block), grid 64 x 64 = 4096.
#define THREADS        256
#define WARPS          8
#define SLAB_COLS4     32               // float4 columns per block (one per lane)
#define NSLAB          (OUT4 / SLAB_COLS4)        // 64 column slabs
#define RGROUPS        64               // row groups (split-K depth)
#define ROWS_PER_BLOCK (IN_SZ / RGROUPS)          // 128
#define ROWS_PER_WARP  (ROWS_PER_BLOCK / WARPS)   // 16

// Deterministic split-K scratch: 64 x 2048 float4 = 2 MB.
__device__ float4 g_partial4[RGROUPS * OUT4];

__global__ __launch_bounds__(THREADS, 1)
void ostl_main_kernel(const float* __restrict__ x,
                      const float* __restrict__ J,
                      const float* __restrict__ W,
                      float* __restrict__ Jout)
{
    __shared__ float  sx[ROWS_PER_BLOCK];              // 512 B
    __shared__ float4 sacc[WARPS][SLAB_COLS4];         // 4 KB

    const int lane = threadIdx.x & 31;
    const int w    = threadIdx.x >> 5;                 // warp 0..7
    const int c    = blockIdx.x * SLAB_COLS4 + lane;   // float4 column
    const int rg0  = blockIdx.y * ROWS_PER_BLOCK;      // block row base

    if (threadIdx.x < ROWS_PER_BLOCK)
        sx[threadIdx.x] = x[rg0 + threadIdx.x];
    __syncthreads();

    const float4* __restrict__ W4 = (const float4*)W;
    const float4* __restrict__ J4 = (const float4*)J;
    float4*       __restrict__ O4 = (float4*)Jout;

    float4 acc = make_float4(0.f, 0.f, 0.f, 0.f);
    const int rbase = w * ROWS_PER_WARP;               // warp's rows within block
    int idx = (rg0 + rbase) * OUT4 + c;                // max ~16.7M -> fits int

    #pragma unroll 16
    for (int r = 0; r < ROWS_PER_WARP; ++r, idx += OUT4) {
        const float xi = sx[rbase + r];
        const float4 wv = W4[idx];
        const float4 jv = J4[idx];

        acc.x = fmaf(xi, wv.x, acc.x);
        acc.y = fmaf(xi, wv.y, acc.y);
        acc.z = fmaf(xi, wv.z, acc.z);
        acc.w = fmaf(xi, wv.w, acc.w);

        float4 o;
        o.x = fmaf(SIG_TAU, jv.x, xi);
        o.y = fmaf(SIG_TAU, jv.y, xi);
        o.z = fmaf(SIG_TAU, jv.z, xi);
        o.w = fmaf(SIG_TAU, jv.w, xi);
        O4[idx] = o;
    }

    // In-block cross-warp reduction in FIXED warp order -> deterministic.
    sacc[w][lane] = acc;
    __syncthreads();

    if (w == 0) {
        float4 a = sacc[0][lane];
        #pragma unroll
        for (int t = 1; t < WARPS; ++t) {
            const float4 b = sacc[t][lane];
            a.x += b.x; a.y += b.y; a.z += b.z; a.w += b.w;
        }
        g_partial4[blockIdx.y * OUT4 + c] = a;
    }
}

// Epilogue (PDL secondary): 16 thread-groups per column, each sums 4 slices in
// fixed order, then fixed-order 16-way combine via shared -> deterministic.
#define EPI_THREADS 256
#define EPI_COLS4   16                       // float4 columns per block
#define EPI_QG      16                       // thread groups per column
#define EPI_SLICES  (RGROUPS / EPI_QG)       // 4 slices per thread
#define EPI_GRID    (OUT4 / EPI_COLS4)       // 128 blocks
__global__ __launch_bounds__(EPI_THREADS, 1)
void ostl_epilogue_kernel(const float* __restrict__ u,
                          float* __restrict__ out_u,
                          float* __restrict__ out_s)
{
    __shared__ float4 sacc[EPI_QG][EPI_COLS4];

    const int lc = threadIdx.x & (EPI_COLS4 - 1);    // local column 0..15
    const int q  = threadIdx.x >> 4;                 // group 0..15
    const int c  = blockIdx.x * EPI_COLS4 + lc;      // float4 column

    // Pre-load u before the dependency sync (input, untouched by main).
    float4 uu = make_float4(0.f, 0.f, 0.f, 0.f);
    if (q == 0) uu = ((const float4*)u)[c];

    cudaGridDependencySynchronize();

    float4 a = make_float4(0.f, 0.f, 0.f, 0.f);
    int idx = (q * EPI_SLICES) * OUT4 + c;
    #pragma unroll
    for (int k = 0; k < EPI_SLICES; ++k, idx += OUT4) {  // 4 loads, fixed order
        const float4 p = g_partial4[idx];
        a.x += p.x; a.y += p.y; a.z += p.z; a.w += p.w;
    }
    sacc[q][lc] = a;
    __syncthreads();

    if (q == 0) {
        a = sacc[0][lc];
        #pragma unroll
        for (int t = 1; t < EPI_QG; ++t) {           // fixed combine order
            const float4 b = sacc[t][lc];
            a.x += b.x; a.y += b.y; a.z += b.z; a.w += b.w;
        }
        float4 uo, so;
        {
            float un;
            un = fmaf(SIG_TAU, uu.x, a.x); so.x = (un - 1.0f) > 0.f ? 1.f : 0.f; uo.x = un - so.x;
            un = fmaf(SIG_TAU, uu.y, a.y); so.y = (un - 1.0f) > 0.f ? 1.f : 0.f; uo.y = un - so.y;
            un = fmaf(SIG_TAU, uu.z, a.z); so.z = (un - 1.0f) > 0.f ? 1.f : 0.f; uo.z = un - so.z;
            un = fmaf(SIG_TAU, uu.w, a.w); so.w = (un - 1.0f) > 0.f ? 1.f : 0.f; uo.w = un - so.w;
        }
        ((float4*)out_u)[c] = uo;
        ((float4*)out_s)[c] = so;
    }
}

extern "C" void kernel_launch(void* const* d_in, const int* in_sizes, int n_in,
                              void* d_out, int out_size)
{
    const float* x = (const float*)d_in[0];
    const float* u = (const float*)d_in[1];
    const float* J = (const float*)d_in[2];
    const float* W = (const float*)d_in[3];

    float* out   = (float*)d_out;
    float* out_u = out;                                   // [0, 8192)
    float* out_J = out + OUT_SZ;                          // [8192, 8192+64M)
    float* out_s = out + OUT_SZ + (size_t)IN_SZ * OUT_SZ; // last 8192

    dim3 grid(NSLAB, RGROUPS);                            // 64 x 64 = 4096 blocks
    ostl_main_kernel<<<grid, THREADS>>>(x, J, W, out_J);

    // PDL launch: epilogue dispatches while main drains.
    cudaLaunchAttribute attrs[1];
    attrs[0].id = cudaLaunchAttributeProgrammaticStreamSerialization;
    attrs[0].val.programmaticStreamSerializationAllowed = 1;

    cudaLaunchConfig_t cfg = {};
    cfg.gridDim  = dim3(EPI_GRID, 1, 1);
    cfg.blockDim = dim3(EPI_THREADS, 1, 1);
    cfg.dynamicSmemBytes = 0;
    cfg.stream   = 0;
    cfg.attrs    = attrs;
    cfg.numAttrs = 1;
    cudaLaunchKernelEx(&cfg, ostl_epilogue_kernel, u, out_u, out_s);
}

// round 17
// speedup vs baseline: 1.1161x; 1.0038x over previous
#include <cuda_runtime.h>

// Problem constants
#define IN_SZ   8192
#define OUT_SZ  8192
#define OUT4    (OUT_SZ / 4)            // 2048 float4 columns
// sigmoid(2.0)
#define SIG_TAU 0.8807970779778823f

// Main-kernel tiling: even SMALLER blocks (drain-ramp shrink, step 2).
// Tile = 32 float4 cols x 64 rows (98 KB traffic/block), grid 64 x 128 = 8192.
#define THREADS        256
#define WARPS          8
#define SLAB_COLS4     32               // float4 columns per block (one per lane)
#define NSLAB          (OUT4 / SLAB_COLS4)        // 64 column slabs
#define RGROUPS        128              // row groups (split-K depth)
#define ROWS_PER_BLOCK (IN_SZ / RGROUPS)          // 64
#define ROWS_PER_WARP  (ROWS_PER_BLOCK / WARPS)   // 8

// Deterministic split-K scratch: 128 x 2048 float4 = 4 MB.
__device__ float4 g_partial4[RGROUPS * OUT4];

__global__ __launch_bounds__(THREADS, 1)
void ostl_main_kernel(const float* __restrict__ x,
                      const float* __restrict__ J,
                      const float* __restrict__ W,
                      float* __restrict__ Jout)
{
    __shared__ float  sx[ROWS_PER_BLOCK];              // 256 B
    __shared__ float4 sacc[WARPS][SLAB_COLS4];         // 4 KB

    const int lane = threadIdx.x & 31;
    const int w    = threadIdx.x >> 5;                 // warp 0..7
    const int c    = blockIdx.x * SLAB_COLS4 + lane;   // float4 column
    const int rg0  = blockIdx.y * ROWS_PER_BLOCK;      // block row base

    if (threadIdx.x < ROWS_PER_BLOCK)
        sx[threadIdx.x] = x[rg0 + threadIdx.x];
    __syncthreads();

    const float4* __restrict__ W4 = (const float4*)W;
    const float4* __restrict__ J4 = (const float4*)J;
    float4*       __restrict__ O4 = (float4*)Jout;

    float4 acc = make_float4(0.f, 0.f, 0.f, 0.f);
    const int rbase = w * ROWS_PER_WARP;               // warp's rows within block
    int idx = (rg0 + rbase) * OUT4 + c;                // max ~16.7M -> fits int

    #pragma unroll
    for (int r = 0; r < ROWS_PER_WARP; ++r, idx += OUT4) {   // 8 iters, 16 loads
        const float xi = sx[rbase + r];
        const float4 wv = W4[idx];
        const float4 jv = J4[idx];

        acc.x = fmaf(xi, wv.x, acc.x);
        acc.y = fmaf(xi, wv.y, acc.y);
        acc.z = fmaf(xi, wv.z, acc.z);
        acc.w = fmaf(xi, wv.w, acc.w);

        float4 o;
        o.x = fmaf(SIG_TAU, jv.x, xi);
        o.y = fmaf(SIG_TAU, jv.y, xi);
        o.z = fmaf(SIG_TAU, jv.z, xi);
        o.w = fmaf(SIG_TAU, jv.w, xi);
        O4[idx] = o;
    }

    // In-block cross-warp reduction in FIXED warp order -> deterministic.
    sacc[w][lane] = acc;
    __syncthreads();

    if (w == 0) {
        float4 a = sacc[0][lane];
        #pragma unroll
        for (int t = 1; t < WARPS; ++t) {
            const float4 b = sacc[t][lane];
            a.x += b.x; a.y += b.y; a.z += b.z; a.w += b.w;
        }
        g_partial4[blockIdx.y * OUT4 + c] = a;
    }
}

// Epilogue (PDL secondary): 16 thread-groups per column, each sums 8 slices in
// fixed order, then fixed-order 16-way combine via shared -> deterministic.
#define EPI_THREADS 256
#define EPI_COLS4   16                       // float4 columns per block
#define EPI_QG      16                       // thread groups per column
#define EPI_SLICES  (RGROUPS / EPI_QG)       // 8 slices per thread
#define EPI_GRID    (OUT4 / EPI_COLS4)       // 128 blocks
__global__ __launch_bounds__(EPI_THREADS, 1)
void ostl_epilogue_kernel(const float* __restrict__ u,
                          float* __restrict__ out_u,
                          float* __restrict__ out_s)
{
    __shared__ float4 sacc[EPI_QG][EPI_COLS4];

    const int lc = threadIdx.x & (EPI_COLS4 - 1);    // local column 0..15
    const int q  = threadIdx.x >> 4;                 // group 0..15
    const int c  = blockIdx.x * EPI_COLS4 + lc;      // float4 column

    // Pre-load u before the dependency sync (input, untouched by main).
    float4 uu = make_float4(0.f, 0.f, 0.f, 0.f);
    if (q == 0) uu = ((const float4*)u)[c];

    cudaGridDependencySynchronize();

    float4 a = make_float4(0.f, 0.f, 0.f, 0.f);
    int idx = (q * EPI_SLICES) * OUT4 + c;
    #pragma unroll
    for (int k = 0; k < EPI_SLICES; ++k, idx += OUT4) {  // 8 loads, fixed order
        const float4 p = g_partial4[idx];
        a.x += p.x; a.y += p.y; a.z += p.z; a.w += p.w;
    }
    sacc[q][lc] = a;
    __syncthreads();

    if (q == 0) {
        a = sacc[0][lc];
        #pragma unroll
        for (int t = 1; t < EPI_QG; ++t) {           // fixed combine order
            const float4 b = sacc[t][lc];
            a.x += b.x; a.y += b.y; a.z += b.z; a.w += b.w;
        }
        float4 uo, so;
        {
            float un;
            un = fmaf(SIG_TAU, uu.x, a.x); so.x = (un - 1.0f) > 0.f ? 1.f : 0.f; uo.x = un - so.x;
            un = fmaf(SIG_TAU, uu.y, a.y); so.y = (un - 1.0f) > 0.f ? 1.f : 0.f; uo.y = un - so.y;
            un = fmaf(SIG_TAU, uu.z, a.z); so.z = (un - 1.0f) > 0.f ? 1.f : 0.f; uo.z = un - so.z;
            un = fmaf(SIG_TAU, uu.w, a.w); so.w = (un - 1.0f) > 0.f ? 1.f : 0.f; uo.w = un - so.w;
        }
        ((float4*)out_u)[c] = uo;
        ((float4*)out_s)[c] = so;
    }
}

extern "C" void kernel_launch(void* const* d_in, const int* in_sizes, int n_in,
                              void* d_out, int out_size)
{
    const float* x = (const float*)d_in[0];
    const float* u = (const float*)d_in[1];
    const float* J = (const float*)d_in[2];
    const float* W = (const float*)d_in[3];

    float* out   = (float*)d_out;
    float* out_u = out;                                   // [0, 8192)
    float* out_J = out + OUT_SZ;                          // [8192, 8192+64M)
    float* out_s = out + OUT_SZ + (size_t)IN_SZ * OUT_SZ; // last 8192

    dim3 grid(NSLAB, RGROUPS);                            // 64 x 128 = 8192 blocks
    ostl_main_kernel<<<grid, THREADS>>>(x, J, W, out_J);

    // PDL launch: epilogue dispatches while main drains.
    cudaLaunchAttribute attrs[1];
    attrs[0].id = cudaLaunchAttributeProgrammaticStreamSerialization;
    attrs[0].val.programmaticStreamSerializationAllowed = 1;

    cudaLaunchConfig_t cfg = {};
    cfg.gridDim  = dim3(EPI_GRID, 1, 1);
    cfg.blockDim = dim3(EPI_THREADS, 1, 1);
    cfg.dynamicSmemBytes = 0;
    cfg.stream   = 0;
    cfg.attrs    = attrs;
    cfg.numAttrs = 1;
    cudaLaunchKernelEx(&cfg, ostl_epilogue_kernel, u, out_u, out_s);
}